// round 2
// baseline (speedup 1.0000x reference)
#include <cuda_runtime.h>

// QuantumConvolution: B=32, Cin=8, Cout=16, H=W=32, K=3, NQ=3, DRC=3, IT=30.
// out[b,cout,i,j] = sum_cin <Z_wire2> of a 3-qubit circuit with
//   per-layer: RY(x*param) on each qubit, Rot(weights) on each qubit, CNOT ring.

#define BB    32
#define CIN   8
#define COUT  16
#define HW    32
#define ITDIM 30
#define NPOS  (ITDIM * ITDIM)   // 900
#define NTHREADS 256

__global__ __launch_bounds__(NTHREADS)
void qconv_kernel(const float* __restrict__ inputs,        // [32][8][32][32]
                  const float* __restrict__ input_params,  // [16][8][3][3]
                  const float* __restrict__ weights,       // [16][8][3][3][3]
                  float* __restrict__ out)                 // [32][16][30][30]
{
    __shared__ float  s_in[CIN][HW][HW + 1];   // padded rows: conflict-light window reads
    __shared__ float  s_pm[CIN][9];            // 0.5 * input_params (half-angle premult)
    __shared__ float4 s_rot[CIN][9][2];        // Rot matrix: {u00r,u00i,u01r,u01i},{u10r,u10i,u11r,u11i}

    const int cout = blockIdx.x;
    const int b    = blockIdx.y;
    const int tid  = threadIdx.x;

    // ---- Load input patch for this batch element (coalesced) ----
    const float* inb = inputs + (size_t)b * (CIN * HW * HW);
    #pragma unroll
    for (int k = 0; k < (CIN * HW * HW) / NTHREADS; k++) {
        int idx = k * NTHREADS + tid;
        int c   = idx >> 10;          // /1024
        int rem = idx & 1023;
        s_in[c][rem >> 5][rem & 31] = inb[idx];
    }

    // ---- Precompute per-(cout,cin,gate) Rot matrices + half params ----
    if (tid < CIN * 9) {
        int cin = tid / 9;
        int g   = tid % 9;
        s_pm[cin][g] = 0.5f * input_params[(cout * CIN + cin) * 9 + g];

        const float* w = weights + (((size_t)cout * CIN + cin) * 9 + g) * 3;
        float phi = w[0], th = w[1], om = w[2];
        float st, ct;  sincosf(0.5f * th, &st, &ct);
        float sa, ca;  sincosf(0.5f * (phi + om), &sa, &ca);   // ep = exp(-i a) = (ca, -sa)
        float sb, cb;  sincosf(0.5f * (phi - om), &sb, &cb);   // em = exp(+i b) = (cb, sb)
        // u00 = ep*c,  u01 = -em*s,  u10 = conj(em)*s,  u11 = conj(ep)*c
        s_rot[cin][g][0] = make_float4( ca * ct, -sa * ct, -cb * st, -sb * st);
        s_rot[cin][g][1] = make_float4( cb * st, -sb * st,  ca * ct,  sa * ct);
    }
    __syncthreads();

    for (int pos = tid; pos < NPOS; pos += NTHREADS) {
        const int i = pos / ITDIM;
        const int j = pos % ITDIM;
        float acc = 0.f;

        #pragma unroll 1
        for (int cin = 0; cin < CIN; cin++) {
            // window pixels: x[l*3+q] = inputs[b,cin,i+l,j+q]
            float x[9], pm[9];
            #pragma unroll
            for (int l = 0; l < 3; l++)
                #pragma unroll
                for (int q = 0; q < 3; q++)
                    x[l * 3 + q] = s_in[cin][i + l][j + q];
            #pragma unroll
            for (int g = 0; g < 9; g++) pm[g] = s_pm[cin][g];

            // state |000>
            float sr[8], si[8];
            #pragma unroll
            for (int a = 0; a < 8; a++) { sr[a] = 0.f; si[a] = 0.f; }
            sr[0] = 1.f;

            #pragma unroll
            for (int l = 0; l < 3; l++) {
                // ---- RY(theta) on each wire ----
                #pragma unroll
                for (int q = 0; q < 3; q++) {
                    float halfth = x[l * 3 + q] * pm[l * 3 + q];
                    float sn, cs;
                    __sincosf(halfth, &sn, &cs);
                    const int st = 4 >> q;
                    #pragma unroll
                    for (int a = 0; a < 8; a++) {
                        if ((a & st) == 0) {
                            int p2 = a | st;
                            float x0r = sr[a],  x0i = si[a];
                            float x1r = sr[p2], x1i = si[p2];
                            sr[a]  = cs * x0r - sn * x1r;
                            si[a]  = cs * x0i - sn * x1i;
                            sr[p2] = sn * x0r + cs * x1r;
                            si[p2] = sn * x0i + cs * x1i;
                        }
                    }
                }
                // ---- Rot(phi,theta,omega) on each wire ----
                #pragma unroll
                for (int q = 0; q < 3; q++) {
                    float4 u0 = s_rot[cin][l * 3 + q][0];
                    float4 u1 = s_rot[cin][l * 3 + q][1];
                    const int st = 4 >> q;
                    #pragma unroll
                    for (int a = 0; a < 8; a++) {
                        if ((a & st) == 0) {
                            int p2 = a | st;
                            float x0r = sr[a],  x0i = si[a];
                            float x1r = sr[p2], x1i = si[p2];
                            sr[a]  = u0.x * x0r - u0.y * x0i + u0.z * x1r - u0.w * x1i;
                            si[a]  = u0.x * x0i + u0.y * x0r + u0.z * x1i + u0.w * x1r;
                            sr[p2] = u1.x * x0r - u1.y * x0i + u1.z * x1r - u1.w * x1i;
                            si[p2] = u1.x * x0i + u1.y * x0r + u1.z * x1i + u1.w * x1r;
                        }
                    }
                }
                // ---- CNOT ring: (0->1), (1->2), (2->0) ---- (register permutation)
                {
                    float t;
                    // CNOT c=0,t=1: swap (4,6),(5,7)
                    t = sr[4]; sr[4] = sr[6]; sr[6] = t;  t = si[4]; si[4] = si[6]; si[6] = t;
                    t = sr[5]; sr[5] = sr[7]; sr[7] = t;  t = si[5]; si[5] = si[7]; si[7] = t;
                    // CNOT c=1,t=2: swap (2,3),(6,7)
                    t = sr[2]; sr[2] = sr[3]; sr[3] = t;  t = si[2]; si[2] = si[3]; si[3] = t;
                    t = sr[6]; sr[6] = sr[7]; sr[7] = t;  t = si[6]; si[6] = si[7]; si[7] = t;
                    // CNOT c=2,t=0: swap (1,5),(3,7)
                    t = sr[1]; sr[1] = sr[5]; sr[5] = t;  t = si[1]; si[1] = si[5]; si[5] = t;
                    t = sr[3]; sr[3] = sr[7]; sr[7] = t;  t = si[3]; si[3] = si[7]; si[7] = t;
                }
            }

            // <Z on wire 2>: + for even amp index, - for odd
            #pragma unroll
            for (int a = 0; a < 8; a++) {
                float p2 = sr[a] * sr[a] + si[a] * si[a];
                acc += (a & 1) ? -p2 : p2;
            }
        }
        out[((size_t)b * COUT + cout) * NPOS + pos] = acc;
    }
}

extern "C" void kernel_launch(void* const* d_in, const int* in_sizes, int n_in,
                              void* d_out, int out_size)
{
    const float* inputs       = (const float*)d_in[0];
    const float* input_params = (const float*)d_in[1];
    const float* weights      = (const float*)d_in[2];
    float* out = (float*)d_out;

    dim3 grid(COUT, BB);   // (cout, b)
    qconv_kernel<<<grid, NTHREADS>>>(inputs, input_params, weights, out);
}

// round 3
// speedup vs baseline: 1.1134x; 1.1134x over previous
#include <cuda_runtime.h>

// QuantumConvolution: B=32, Cin=8, Cout=16, H=W=32, K=3, NQ=3, DRC=3, IT=30.
// R3: packed fma.rn.f32x2 complex arithmetic, layer-0 |000> sparsity,
//     cin distributed across lanes (tid&7) with shuffle reduction.

#define BB    32
#define CIN   8
#define COUT  16
#define HW    32
#define ITDIM 30
#define NPOS  (ITDIM * ITDIM)   // 900
#define NTHREADS 256
#define CH_STRIDE 1060          // per-channel smem floats: 32*33=1056 (+4 pad) => cin lanes hit distinct banks
#define RP_STRIDE 39            // ulonglong2 per cin: 9 gates * 4 + 2 (gate0 real-packs) + pad

typedef unsigned long long ull;

__device__ __forceinline__ ull pk2(float lo, float hi) {
    ull r; asm("mov.b64 %0, {%1, %2};" : "=l"(r) : "f"(lo), "f"(hi)); return r;
}
__device__ __forceinline__ ull bc2(float v) { return pk2(v, v); }
__device__ __forceinline__ ull swap2(ull a) {
    ull r;
    asm("{\n\t.reg .b32 lo, hi;\n\tmov.b64 {lo, hi}, %1;\n\tmov.b64 %0, {hi, lo};\n\t}"
        : "=l"(r) : "l"(a));
    return r;
}
__device__ __forceinline__ ull fma2(ull a, ull b, ull c) {
    ull d; asm("fma.rn.f32x2 %0, %1, %2, %3;" : "=l"(d) : "l"(a), "l"(b), "l"(c)); return d;
}
__device__ __forceinline__ ull mul2(ull a, ull b) {
    ull d; asm("mul.rn.f32x2 %0, %1, %2;" : "=l"(d) : "l"(a), "l"(b)); return d;
}
__device__ __forceinline__ void upk2(ull a, float& lo, float& hi) {
    asm("mov.b64 {%0, %1}, %2;" : "=f"(lo), "=f"(hi) : "l"(a));
}
__device__ __forceinline__ ull mkpk(float lo, float hi) {
    return (ull)__float_as_uint(lo) | ((ull)__float_as_uint(hi) << 32);
}

__global__ __launch_bounds__(NTHREADS)
void qconv_kernel(const float* __restrict__ inputs,        // [32][8][32][32]
                  const float* __restrict__ input_params,  // [16][8][3][3]
                  const float* __restrict__ weights,       // [16][8][3][3][3]
                  float* __restrict__ out)                 // [32][16][30][30]
{
    __shared__ float      s_in[CIN * CH_STRIDE];     // padded channel stride: conflict-free cin lanes
    __shared__ float      s_pm[CIN][9];              // 0.5 * input_params
    __shared__ ulonglong2 s_rp[CIN][RP_STRIDE];      // packed Rot constants

    const int cout = blockIdx.x;
    const int b    = blockIdx.y;
    const int tid  = threadIdx.x;
    const int cin  = tid & 7;        // lane's input channel
    const int grp  = tid >> 3;       // 32 position groups

    // ---- Load input patch (float4, coalesced) into padded smem ----
    const float4* inb4 = (const float4*)(inputs + (size_t)b * (CIN * HW * HW));
    #pragma unroll
    for (int k = 0; k < 8; k++) {
        int idx = k * NTHREADS + tid;        // 2048 float4 total
        int c   = idx >> 8;                  // 256 float4 per channel
        int rem = idx & 255;
        int row = rem >> 3;
        int col = (rem & 7) * 4;
        float4 v = inb4[idx];
        float* dst = &s_in[c * CH_STRIDE + row * 33 + col];
        dst[0] = v.x; dst[1] = v.y; dst[2] = v.z; dst[3] = v.w;
    }

    // ---- Precompute packed Rot constants + half params ----
    if (tid < CIN * 9) {
        int pc = tid / 9;
        int g  = tid % 9;
        s_pm[pc][g] = 0.5f * input_params[(cout * CIN + pc) * 9 + g];

        const float* w = weights + (((size_t)cout * CIN + pc) * 9 + g) * 3;
        float phi = w[0], th = w[1], om = w[2];
        float st, ct;  sincosf(0.5f * th, &st, &ct);
        float sa, ca;  sincosf(0.5f * (phi + om), &sa, &ca);
        float sb, cb;  sincosf(0.5f * (phi - om), &sb, &cb);
        // u00 = ( ca*ct, -sa*ct)   u01 = (-cb*st, -sb*st)
        // u10 = ( cb*st, -sb*st)   u11 = ( ca*ct,  sa*ct)
        float u00r =  ca * ct, u00i = -sa * ct;
        float u01r = -cb * st, u01i = -sb * st;
        float u10r =  cb * st, u10i = -sb * st;
        float u11r =  ca * ct, u11i =  sa * ct;
        ulonglong2 e;
        e.x = mkpk(u00r, u00r); e.y = mkpk(-u00i, u00i); s_rp[pc][g * 4 + 0] = e;
        e.x = mkpk(u01r, u01r); e.y = mkpk(-u01i, u01i); s_rp[pc][g * 4 + 1] = e;
        e.x = mkpk(u10r, u10r); e.y = mkpk(-u10i, u10i); s_rp[pc][g * 4 + 2] = e;
        e.x = mkpk(u11r, u11r); e.y = mkpk(-u11i, u11i); s_rp[pc][g * 4 + 3] = e;
        if (g == 0) {  // real-input packs for layer-0 qubit-0 Rot
            e.x = mkpk(u00r, u00i); e.y = mkpk(u01r, u01i); s_rp[pc][36] = e;
            e.x = mkpk(u10r, u10i); e.y = mkpk(u11r, u11i); s_rp[pc][37] = e;
        }
    }
    __syncthreads();

    const float* chan = &s_in[cin * CH_STRIDE];
    float pm[9];
    #pragma unroll
    for (int g = 0; g < 9; g++) pm[g] = s_pm[cin][g];

    for (int pos = grp; pos < NPOS; pos += 32) {
        const int i = pos / ITDIM;
        const int j = pos % ITDIM;

        float x[9];
        #pragma unroll
        for (int l = 0; l < 3; l++)
            #pragma unroll
            for (int q = 0; q < 3; q++)
                x[l * 3 + q] = chan[(i + l) * 33 + (j + q)];

        ull s[8];

        // ======== Layer 0 (sparse |000> fast path) ========
        {
            float sn0, cs0, sn1, cs1, sn2c, cs2c;
            __sincosf(x[0] * pm[0], &sn0, &cs0);
            __sincosf(x[1] * pm[1], &sn1, &cs1);
            __sincosf(x[2] * pm[2], &sn2c, &cs2c);
            // real product state after RY x RY x RY
            float t0 = cs0 * cs1, t1 = cs0 * sn1, t2 = sn0 * cs1, t3 = sn0 * sn1;
            float r0 = t0 * cs2c, r1 = t0 * sn2c, r2 = t1 * cs2c, r3 = t1 * sn2c;
            float r4 = t2 * cs2c, r5 = t2 * sn2c, r6 = t3 * cs2c, r7 = t3 * sn2c;

            // Rot on qubit 0 (stride 4), real inputs
            ulonglong2 ra = s_rp[cin][36];   // {pk(u00), pk(u01)}
            ulonglong2 rb = s_rp[cin][37];   // {pk(u10), pk(u11)}
            ull b0 = bc2(r0), b1 = bc2(r1), b2 = bc2(r2), b3 = bc2(r3);
            ull b4 = bc2(r4), b5 = bc2(r5), b6 = bc2(r6), b7 = bc2(r7);
            s[0] = fma2(ra.y, b4, mul2(ra.x, b0));
            s[4] = fma2(rb.y, b4, mul2(rb.x, b0));
            s[1] = fma2(ra.y, b5, mul2(ra.x, b1));
            s[5] = fma2(rb.y, b5, mul2(rb.x, b1));
            s[2] = fma2(ra.y, b6, mul2(ra.x, b2));
            s[6] = fma2(rb.y, b6, mul2(rb.x, b2));
            s[3] = fma2(ra.y, b7, mul2(ra.x, b3));
            s[7] = fma2(rb.y, b7, mul2(rb.x, b3));
        }

        // General complex Rot gate: s[a], s[p] <- U * (s[a], s[p])
        #define ROT_GATE(G, ST)                                                     \
        {                                                                           \
            ulonglong2 c0 = s_rp[cin][(G) * 4 + 0];                                 \
            ulonglong2 c1 = s_rp[cin][(G) * 4 + 1];                                 \
            ulonglong2 c2 = s_rp[cin][(G) * 4 + 2];                                 \
            ulonglong2 c3 = s_rp[cin][(G) * 4 + 3];                                 \
            _Pragma("unroll")                                                       \
            for (int a = 0; a < 8; a++) {                                           \
                if ((a & (ST)) == 0) {                                              \
                    int p = a | (ST);                                               \
                    ull x0 = s[a], x1 = s[p];                                       \
                    ull x0s = swap2(x0), x1s = swap2(x1);                           \
                    s[a] = fma2(c1.y, x1s, fma2(c1.x, x1,                           \
                             fma2(c0.y, x0s, mul2(c0.x, x0))));                     \
                    s[p] = fma2(c3.y, x1s, fma2(c3.x, x1,                           \
                             fma2(c2.y, x0s, mul2(c2.x, x0))));                     \
                }                                                                   \
            }                                                                       \
        }

        // RY gate (same real rotation applied to re & im halves)
        #define RY_GATE(G, ST)                                                      \
        {                                                                           \
            float sn, cs;                                                           \
            __sincosf(x[(G)] * pm[(G)], &sn, &cs);                                  \
            ull cs2 = bc2(cs), sn2 = bc2(sn), nsn2 = bc2(-sn);                      \
            _Pragma("unroll")                                                       \
            for (int a = 0; a < 8; a++) {                                           \
                if ((a & (ST)) == 0) {                                              \
                    int p = a | (ST);                                               \
                    ull x0 = s[a], x1 = s[p];                                       \
                    s[a] = fma2(nsn2, x1, mul2(cs2, x0));                           \
                    s[p] = fma2(sn2,  x0, mul2(cs2, x1));                           \
                }                                                                   \
            }                                                                       \
        }

        #define CNOT_RING()                                                         \
        {                                                                           \
            ull t;                                                                  \
            t = s[4]; s[4] = s[6]; s[6] = t;  t = s[5]; s[5] = s[7]; s[7] = t;      \
            t = s[2]; s[2] = s[3]; s[3] = t;  t = s[6]; s[6] = s[7]; s[7] = t;      \
            t = s[1]; s[1] = s[5]; s[5] = t;  t = s[3]; s[3] = s[7]; s[7] = t;      \
        }

        // finish layer 0: Rot on qubits 1, 2, then CNOT ring
        ROT_GATE(1, 2)
        ROT_GATE(2, 1)
        CNOT_RING()

        // ======== Layer 1 ========
        RY_GATE(3, 4)  RY_GATE(4, 2)  RY_GATE(5, 1)
        ROT_GATE(3, 4) ROT_GATE(4, 2) ROT_GATE(5, 1)
        CNOT_RING()

        // ======== Layer 2 ========
        RY_GATE(6, 4)  RY_GATE(7, 2)  RY_GATE(8, 1)
        ROT_GATE(6, 4) ROT_GATE(7, 2) ROT_GATE(8, 1)
        CNOT_RING()

        #undef ROT_GATE
        #undef RY_GATE
        #undef CNOT_RING

        // <Z wire2> = sum_{a even} |amp|^2 - sum_{a odd} |amp|^2
        ull eacc = mul2(s[0], s[0]);
        eacc = fma2(s[2], s[2], eacc);
        eacc = fma2(s[4], s[4], eacc);
        eacc = fma2(s[6], s[6], eacc);
        ull oacc = mul2(s[1], s[1]);
        oacc = fma2(s[3], s[3], oacc);
        oacc = fma2(s[5], s[5], oacc);
        oacc = fma2(s[7], s[7], oacc);
        float er, ei, orr, oi;
        upk2(eacc, er, ei);
        upk2(oacc, orr, oi);
        float acc = (er + ei) - (orr + oi);

        // reduce over the 8 cin lanes
        acc += __shfl_xor_sync(0xFFFFFFFFu, acc, 1);
        acc += __shfl_xor_sync(0xFFFFFFFFu, acc, 2);
        acc += __shfl_xor_sync(0xFFFFFFFFu, acc, 4);
        if (cin == 0)
            out[((size_t)b * COUT + cout) * NPOS + pos] = acc;
    }
}

extern "C" void kernel_launch(void* const* d_in, const int* in_sizes, int n_in,
                              void* d_out, int out_size)
{
    const float* inputs       = (const float*)d_in[0];
    const float* input_params = (const float*)d_in[1];
    const float* weights      = (const float*)d_in[2];
    float* out = (float*)d_out;

    dim3 grid(COUT, BB);   // (cout, b)
    qconv_kernel<<<grid, NTHREADS>>>(inputs, input_params, weights, out);
}